// round 13
// baseline (speedup 1.0000x reference)
#include <cuda_runtime.h>
#include <cuda_fp16.h>
#include <math.h>

#define BB 512
#define SS 512
#define VV 50000
#define DD 300
#define PP 3
#define D4 75   // DD/4
#define CE 30   // e per chunk
#define NBLK 256
#define NPREP 71
#define NT 384

// ---------------- accumulator block (zeroed in-kernel) ----------------
#define ACCN 11104
__device__ __align__(16) float g_acc[ACCN];
#define pU   (g_acc + 0)
#define pV   (g_acc + 300)
#define pU2  (g_acc + 600)
#define pB1  (g_acc + 900)
#define pB2  (g_acc + 1200)
#define pP1  (g_acc + 1500)
#define pP2  (g_acc + 1800)
#define pA1  (g_acc + 2100)
#define pA2  (g_acc + 2400)
#define pBCV (g_acc + 2700)
#define pG   (g_acc + 3000)
#define pE   (g_acc + 3900)
#define pH   (g_acc + 4800)
#define pF   (g_acc + 5700)
#define pJ   (g_acc + 6600)
#define pM2  (g_acc + 7500)
#define pM1  (g_acc + 8400)
#define pM0  (g_acc + 9300)
#define pMX  (g_acc + 10200)
#define pCV  (g_acc + 11100)

__device__ float g_ck, g_cq, g_c2, g_cc1, g_cc2;
__device__ __align__(16) float4 g_svt[VV];              // {sv, t1, t2, 0}
__device__ __align__(16) uint2 g_embh[(size_t)VV * D4]; // fp16 emb shadow

// ---------------- replay-safe grid barrier (variable participant count) -----
__device__ volatile unsigned g_barphase[8];
__device__ unsigned g_barcnt[8];

__device__ __forceinline__ void gridbar(int slot, unsigned count) {
    __syncthreads();
    if (threadIdx.x == 0) {
        __threadfence();
        unsigned ph = g_barphase[slot];
        unsigned t = atomicAdd(&g_barcnt[slot], 1u);
        if (t == count - 1) {
            g_barcnt[slot] = 0;            // reset for next replay
            __threadfence();
            atomicAdd((unsigned*)&g_barphase[slot], 1u);
        } else {
            while (g_barphase[slot] == ph) { __nanosleep(32); }
        }
        __threadfence();
    }
    __syncthreads();
}

// ---------------- device helpers ----------------
__device__ __forceinline__ float lanedot(const float* __restrict__ a,
                                         const float* __restrict__ b, int lane) {
    float s = 0.f;
    for (int e = lane; e < DD; e += 32) s += a[e] * b[e];
#pragma unroll
    for (int o = 16; o; o >>= 1) s += __shfl_xor_sync(0xffffffffu, s, o);
    return s;
}

// out[f] += sum_{e in chunk} M[e*DD+f] * y[e]
__device__ __forceinline__ void mv_part(const float* __restrict__ M,
                                        const float* __restrict__ y,
                                        float* __restrict__ out, int chunk) {
    __shared__ float sy[CE];
    int t = threadIdx.x;
    if (t < CE) sy[t] = y[chunk * CE + t];
    __syncthreads();
    if (t < DD) {
        float acc = 0.f;
        const float* Mp = M + chunk * CE * DD + t;
#pragma unroll
        for (int e = 0; e < CE; e++) acc += Mp[e * DD] * sy[e];
        atomicAdd(out + t, acc);
    }
    __syncthreads();
}

// out[p][f] += sum_{e in chunk} A[p*DD+e] * B[e*DD+f]  for p=0..2
__device__ __forceinline__ void mm3_part(const float* __restrict__ A,
                                         const float* __restrict__ B,
                                         float* __restrict__ out, int chunk) {
    __shared__ float sa[3][CE];
    int t = threadIdx.x;
    if (t < 3 * CE) sa[t / CE][t % CE] = A[(t / CE) * DD + chunk * CE + (t % CE)];
    __syncthreads();
    if (t < DD) {
        float a0 = 0.f, a1 = 0.f, a2 = 0.f;
        const float* Bp = B + chunk * CE * DD + t;
#pragma unroll
        for (int e = 0; e < CE; e++) {
            float b = Bp[e * DD];
            a0 += sa[0][e] * b; a1 += sa[1][e] * b; a2 += sa[2][e] * b;
        }
        atomicAdd(out + t, a0);
        atomicAdd(out + DD + t, a1);
        atomicAdd(out + 2 * DD + t, a2);
    }
    __syncthreads();
}

// ============================================================
// ONE persistent kernel: prep(5 levels) || shadow, then svt, then paired mega.
// ============================================================
__global__ __launch_bounds__(NT, 2) void k_all(
        const float* __restrict__ Wq, const float* __restrict__ Wk,
        const float* __restrict__ Wp, const float* __restrict__ Wx,
        const float* __restrict__ Wd, const float* __restrict__ wmlp,
        const float* __restrict__ bk, const float* __restrict__ bq,
        const float* __restrict__ bp, const float* __restrict__ bx,
        const float* __restrict__ bd, const float* __restrict__ emb,
        const int* __restrict__ text, const int* __restrict__ asp,
        float* __restrict__ out) {
    int b = blockIdx.x, tid = threadIdx.x;
    int lane = tid & 31, wid = tid >> 5;

    // shared memory (46.4 KB static; aliases documented below)
    __shared__ int   s_idx[2][SS];
    __shared__ int   s_asp[2][8];
    __shared__ int   s_len[2];
    __shared__ float s_sv[2][SS], s_t1[2][SS], s_t2[2][SS];
    __shared__ __align__(16) float s_c0[2][SS];   // phase B aliases sV/sA1/sA2 here
    __shared__ float s_c1[2][SS], s_c2[2][SS];
    __shared__ __align__(16) float s_x0[2][DD];
    __shared__ __align__(16) float4 s_part[3][4][D4];  // s_am[a] aliases s_part[a][0]
    __shared__ float s_red[12][6];
    __shared__ float s_b[12];

    float4* sV  = reinterpret_cast<float4*>(&s_c0[0][0]);        // [0,1200)B
    float4* sA1 = reinterpret_cast<float4*>(&s_c0[0][0]) + D4;   // [1200,2400)B
    float4* sA2 = reinterpret_cast<float4*>(&s_c0[0][0]) + 2 * D4;

    // ================= phase A: prep chain (blocks < NPREP) or shadow =======
    if (b < NPREP) {
        for (int i = b * NT + tid; i < ACCN; i += NPREP * NT) g_acc[i] = 0.f;
        gridbar(0, NPREP);

        // level 1: u, v, G, E, bcv, ck/cq
        if (b < 10) {
            mv_part(Wq, wmlp + DD, pU, b);
        } else if (b < 20) {
            mv_part(Wk, wmlp, pV, b - 10);
        } else if (b < 30) {
            mm3_part(Wd, Wp, pG, b - 20);
        } else if (b < 40) {
            mm3_part(Wd, Wx, pE, b - 30);
        } else if (b < 70) {
            if (wid < 10) {
                int row = (b - 40) * 10 + wid;
                float s = lanedot(Wp + row * DD, bk, lane);
                if (lane == 0) pBCV[row] = s + bp[row] + bx[row];
            }
        } else {
            if (wid == 0) { float s = lanedot(bk, wmlp, lane); if (lane == 0) g_ck = s; }
            if (wid == 1) { float s = lanedot(bq, wmlp + DD, lane); if (lane == 0) g_cq = s; }
        }
        gridbar(1, NPREP);

        // level 2: u2, M2, H, F, c2
        if (b < 10) {
            mv_part(Wx, pU, pU2, b);
        } else if (b < 20) {
            mm3_part(pG, Wk, pM2, b - 10);
        } else if (b < 30) {
            mm3_part(pE, Wp, pH, b - 20);
        } else if (b < 40) {
            mm3_part(pE, Wx, pF, b - 30);
        } else if (b == 40) {
            if (wid == 0) { float s = lanedot(bx, pU, lane); if (lane == 0) g_c2 = s + g_cq; }
        }
        gridbar(2, NPREP);

        // level 3: b1, p1, M1, Mx, J, cc1, cvec
        if (b < 10) {
            mv_part(Wx, pU2, pB1, b);
        } else if (b < 20) {
            mv_part(Wp, pU2, pP1, b - 10);
        } else if (b < 30) {
            mm3_part(pH, Wk, pM1, b - 20);
        } else if (b < 40) {
            mm3_part(pF, Wx, pMX, b - 30);
        } else if (b < 50) {
            mm3_part(pF, Wp, pJ, b - 40);
        } else if (b == 50) {
            if (wid == 0) { float s = lanedot(pBCV, pU2, lane); if (lane == 0) s_b[0] = s; }
            if (wid >= 1 && wid <= 3) {
                int p = wid - 1;
                float s = 0.f;
                for (int e = lane; e < DD; e += 32)
                    s += (Wd[p * DD + e] + pE[p * DD + e] + pF[p * DD + e]) * pBCV[e];
#pragma unroll
                for (int o = 16; o; o >>= 1) s += __shfl_xor_sync(0xffffffffu, s, o);
                if (lane == 0) pCV[p] = s + bd[p];
            }
            __syncthreads();
            if (tid == 0) g_cc1 = s_b[0] + g_c2;
            __syncthreads();
        }
        gridbar(3, NPREP);

        // level 4: a1, b2, p2, M0, cc2
        if (b < 10) {
            mv_part(Wk, pP1, pA1, b);
        } else if (b < 20) {
            mv_part(Wx, pB1, pB2, b - 10);
        } else if (b < 30) {
            mv_part(Wp, pB1, pP2, b - 20);
        } else if (b < 40) {
            mm3_part(pJ, Wk, pM0, b - 30);
        } else if (b == 40) {
            if (wid == 0) { float s = lanedot(pBCV, pB1, lane); if (lane == 0) g_cc2 = s + g_cc1; }
        }
        gridbar(4, NPREP);

        // level 5: a2
        if (b < 10) mv_part(Wk, pP2, pA2, b);
    } else {
        // ---- fp16 shadow: flat coalesced convert, manual x4 MLP ----
        const int TOT = VV * D4;
        const int NSH = (NBLK - NPREP) * NT;
        const float4* em4 = reinterpret_cast<const float4*>(emb);
        int c = (b - NPREP) * NT + tid;
        for (; c + 3 * NSH < TOT; c += 4 * NSH) {
            float4 e0 = em4[c], e1 = em4[c + NSH], e2 = em4[c + 2 * NSH], e3 = em4[c + 3 * NSH];
            uint2 u0, u1, u2, u3;
            __half2 h;
            h = __floats2half2_rn(e0.x, e0.y); u0.x = *reinterpret_cast<unsigned*>(&h);
            h = __floats2half2_rn(e0.z, e0.w); u0.y = *reinterpret_cast<unsigned*>(&h);
            h = __floats2half2_rn(e1.x, e1.y); u1.x = *reinterpret_cast<unsigned*>(&h);
            h = __floats2half2_rn(e1.z, e1.w); u1.y = *reinterpret_cast<unsigned*>(&h);
            h = __floats2half2_rn(e2.x, e2.y); u2.x = *reinterpret_cast<unsigned*>(&h);
            h = __floats2half2_rn(e2.z, e2.w); u2.y = *reinterpret_cast<unsigned*>(&h);
            h = __floats2half2_rn(e3.x, e3.y); u3.x = *reinterpret_cast<unsigned*>(&h);
            h = __floats2half2_rn(e3.z, e3.w); u3.y = *reinterpret_cast<unsigned*>(&h);
            g_embh[c] = u0; g_embh[c + NSH] = u1;
            g_embh[c + 2 * NSH] = u2; g_embh[c + 3 * NSH] = u3;
        }
        for (; c < TOT; c += NSH) {
            float4 e = em4[c];
            uint2 u; __half2 h;
            h = __floats2half2_rn(e.x, e.y); u.x = *reinterpret_cast<unsigned*>(&h);
            h = __floats2half2_rn(e.z, e.w); u.y = *reinterpret_cast<unsigned*>(&h);
            g_embh[c] = u;
        }
    }
    gridbar(5, NBLK);

    // ================= phase B: svt from fp16 shadow ========================
    if (tid < D4) {
        sV[tid]  = reinterpret_cast<const float4*>(pV)[tid];
        sA1[tid] = reinterpret_cast<const float4*>(pA1)[tid];
        sA2[tid] = reinterpret_cast<const float4*>(pA2)[tid];
    }
    __syncthreads();
    for (int row = b * 12 + wid; row < VV; row += NBLK * 12) {
        const uint2* er = g_embh + (size_t)row * D4;
        float av = 0.f, a1 = 0.f, a2 = 0.f;
#pragma unroll
        for (int i = lane; i < D4; i += 32) {
            uint2 u = er[i];
            float2 lo = __half22float2(*reinterpret_cast<__half2*>(&u.x));
            float2 hi = __half22float2(*reinterpret_cast<__half2*>(&u.y));
            float4 vv = sV[i], w1 = sA1[i], w2 = sA2[i];
            av += lo.x * vv.x + lo.y * vv.y + hi.x * vv.z + hi.y * vv.w;
            a1 += lo.x * w1.x + lo.y * w1.y + hi.x * w1.z + hi.y * w1.w;
            a2 += lo.x * w2.x + lo.y * w2.y + hi.x * w2.z + hi.y * w2.w;
        }
#pragma unroll
        for (int o = 16; o; o >>= 1) {
            av += __shfl_xor_sync(0xffffffffu, av, o);
            a1 += __shfl_xor_sync(0xffffffffu, a1, o);
            a2 += __shfl_xor_sync(0xffffffffu, a2, o);
        }
        if (lane == 0) g_svt[row] = make_float4(av, a1, a2, 0.f);
    }
    gridbar(6, NBLK);

    // ================= phase C: paired mega (rows b and b+NBLK) =============
    const int rowA = b, rowB = b + NBLK;

    if (tid < 16) {
        int r = tid >> 3;
        s_asp[r][tid & 7] = asp[(r ? rowB : rowA) * 8 + (tid & 7)];
    }
    int cntA = 0, cntB = 0;
    for (int s = tid; s < SS; s += NT) {
        int ixA = text[rowA * SS + s];
        int ixB = text[rowB * SS + s];
        s_idx[0][s] = ixA; cntA += (ixA != 0);
        s_idx[1][s] = ixB; cntB += (ixB != 0);
        float4 tA = g_svt[ixA];
        float4 tB = g_svt[ixB];
        s_sv[0][s] = tA.x; s_t1[0][s] = tA.y; s_t2[0][s] = tA.z;
        s_sv[1][s] = tB.x; s_t1[1][s] = tB.y; s_t2[1][s] = tB.z;
    }
#pragma unroll
    for (int o = 16; o; o >>= 1) {
        cntA += __shfl_xor_sync(0xffffffffu, cntA, o);
        cntB += __shfl_xor_sync(0xffffffffu, cntB, o);
    }
    if (lane == 0) { s_red[wid][0] = (float)cntA; s_red[wid][1] = (float)cntB; }
    __syncthreads();
    if (tid == 0) {
        float a = 0.f, c = 0.f;
        for (int w = 0; w < 12; w++) { a += s_red[w][0]; c += s_red[w][1]; }
        s_len[0] = (int)a; s_len[1] = (int)c;
    }
    // x0 for both rows from fp16 shadow (150 threads)
    if (tid < 2 * D4) {
        int r = tid / D4, ch = tid - r * D4;
        int na = 0;
#pragma unroll
        for (int j = 0; j < 8; j++) na += (s_asp[r][j] != 0);
        float invn = 1.0f / (float)na;
        float4 acc = make_float4(0.f, 0.f, 0.f, 0.f);
#pragma unroll
        for (int j = 0; j < 8; j++) {
            uint2 v = g_embh[(size_t)s_asp[r][j] * D4 + ch];   // row 0 is zeros
            float2 lo = __half22float2(*reinterpret_cast<__half2*>(&v.x));
            float2 hi = __half22float2(*reinterpret_cast<__half2*>(&v.y));
            acc.x += lo.x; acc.y += lo.y; acc.z += hi.x; acc.w += hi.y;
        }
        acc.x *= invn; acc.y *= invn; acc.z *= invn; acc.w *= invn;
        reinterpret_cast<float4*>(s_x0[r])[ch] = acc;
    }
    __syncthreads();

    // x0 dots with u2/b1/b2 for both rows (one serial chain)
    {
        float v0 = 0.f, v1 = 0.f, v2 = 0.f, v3 = 0.f, v4 = 0.f, v5 = 0.f;
        if (tid < DD) {
            float u2v = pU2[tid], b1v = pB1[tid], b2v = pB2[tid];
            float xa = s_x0[0][tid], xb = s_x0[1][tid];
            v0 = xa * u2v; v1 = xa * b1v; v2 = xa * b2v;
            v3 = xb * u2v; v4 = xb * b1v; v5 = xb * b2v;
        }
#pragma unroll
        for (int o = 16; o; o >>= 1) {
            v0 += __shfl_xor_sync(0xffffffffu, v0, o);
            v1 += __shfl_xor_sync(0xffffffffu, v1, o);
            v2 += __shfl_xor_sync(0xffffffffu, v2, o);
            v3 += __shfl_xor_sync(0xffffffffu, v3, o);
            v4 += __shfl_xor_sync(0xffffffffu, v4, o);
            v5 += __shfl_xor_sync(0xffffffffu, v5, o);
        }
        if (lane == 0) {
            s_red[wid][0] = v0; s_red[wid][1] = v1; s_red[wid][2] = v2;
            s_red[wid][3] = v3; s_red[wid][4] = v4; s_red[wid][5] = v5;
        }
    }
    __syncthreads();
    if (tid == 0) {
#pragma unroll
        for (int k = 0; k < 6; k++) {
            float a = 0.f;
            for (int w = 0; w < 12; w++) a += s_red[w][k];
            s_b[k] = a;
        }
    }
    __syncthreads();
    float du2A = s_b[0], db1A = s_b[1], db2A = s_b[2];
    float du2B = s_b[3], db1B = s_b[4], db2B = s_b[5];

    int lenA = s_len[0], lenB = s_len[1];
    int s0A = SS - lenA, s0B = SS - lenB;
    float invlenA = 1.0f / (float)lenA, invlenB = 1.0f / (float)lenB;

    // ---- hop 0 (both rows) ----
    float ckq0A = g_ck + du2A + g_c2;
    float ckq0B = g_ck + du2B + g_c2;
    {
        float eA = 0.f, s1A = 0.f, s2A = 0.f, eB = 0.f, s1B = 0.f, s2B = 0.f;
        for (int s = s0A + tid; s < SS; s += NT) {
            float w = 1.0f - (float)(s - s0A) * invlenA;
            float e = expf(tanhf(w * s_sv[0][s] + ckq0A));
            float ew = e * w;
            s_c0[0][s] = ew;
            eA += e; s1A += ew * s_t1[0][s]; s2A += ew * s_t2[0][s];
        }
        for (int s = s0B + tid; s < SS; s += NT) {
            float w = 1.0f - (float)(s - s0B) * invlenB;
            float e = expf(tanhf(w * s_sv[1][s] + ckq0B));
            float ew = e * w;
            s_c0[1][s] = ew;
            eB += e; s1B += ew * s_t1[1][s]; s2B += ew * s_t2[1][s];
        }
#pragma unroll
        for (int o = 16; o; o >>= 1) {
            eA += __shfl_xor_sync(0xffffffffu, eA, o);
            s1A += __shfl_xor_sync(0xffffffffu, s1A, o);
            s2A += __shfl_xor_sync(0xffffffffu, s2A, o);
            eB += __shfl_xor_sync(0xffffffffu, eB, o);
            s1B += __shfl_xor_sync(0xffffffffu, s1B, o);
            s2B += __shfl_xor_sync(0xffffffffu, s2B, o);
        }
        if (lane == 0) {
            s_red[wid][0] = eA; s_red[wid][1] = s1A; s_red[wid][2] = s2A;
            s_red[wid][3] = eB; s_red[wid][4] = s1B; s_red[wid][5] = s2B;
        }
    }
    __syncthreads();
    if (tid == 0) {
        float t[6] = {};
        for (int w = 0; w < 12; w++)
#pragma unroll
            for (int k = 0; k < 6; k++) t[k] += s_red[w][k];
        float invA = 1.0f / (t[0] + (float)s0A * expf(tanhf(ckq0A)));
        float invB = 1.0f / (t[3] + (float)s0B * expf(tanhf(ckq0B)));
        s_b[0] = invA; s_b[1] = invA * t[1]; s_b[2] = invA * t[2];
        s_b[3] = invB; s_b[4] = invB * t[4]; s_b[5] = invB * t[5];
    }
    __syncthreads();
    float inv0A = s_b[0], inv0B = s_b[3];
    float am02A = s_b[2], am02B = s_b[5];
    float q1A = s_b[1] + db1A + g_cc1;
    float q1B = s_b[4] + db1B + g_cc1;

    // ---- hop 1 (both rows) ----
    float ckq1A = g_ck + q1A, ckq1B = g_ck + q1B;
    {
        float eA = 0.f, s1A = 0.f, eB = 0.f, s1B = 0.f;
        for (int s = s0A + tid; s < SS; s += NT) {
            float w = 1.0f - (float)(s - s0A) * invlenA;
            float e = expf(tanhf(w * s_sv[0][s] + ckq1A));
            float ew = e * w;
            s_c1[0][s] = ew;
            eA += e; s1A += ew * s_t1[0][s];
        }
        for (int s = s0B + tid; s < SS; s += NT) {
            float w = 1.0f - (float)(s - s0B) * invlenB;
            float e = expf(tanhf(w * s_sv[1][s] + ckq1B));
            float ew = e * w;
            s_c1[1][s] = ew;
            eB += e; s1B += ew * s_t1[1][s];
        }
#pragma unroll
        for (int o = 16; o; o >>= 1) {
            eA += __shfl_xor_sync(0xffffffffu, eA, o);
            s1A += __shfl_xor_sync(0xffffffffu, s1A, o);
            eB += __shfl_xor_sync(0xffffffffu, eB, o);
            s1B += __shfl_xor_sync(0xffffffffu, s1B, o);
        }
        if (lane == 0) {
            s_red[wid][0] = eA; s_red[wid][1] = s1A;
            s_red[wid][2] = eB; s_red[wid][3] = s1B;
        }
    }
    __syncthreads();
    if (tid == 0) {
        float t[4] = {};
        for (int w = 0; w < 12; w++)
#pragma unroll
            for (int k = 0; k < 4; k++) t[k] += s_red[w][k];
        float invA = 1.0f / (t[0] + (float)s0A * expf(tanhf(ckq1A)));
        float invB = 1.0f / (t[2] + (float)s0B * expf(tanhf(ckq1B)));
        s_b[0] = invA; s_b[1] = invA * t[1];
        s_b[2] = invB; s_b[3] = invB * t[3];
    }
    __syncthreads();
    float inv1A = s_b[0], inv1B = s_b[2];
    float q2A = s_b[1] + am02A + db2A + g_cc2;
    float q2B = s_b[3] + am02B + db2B + g_cc2;

    // ---- hop 2 (both rows) ----
    float ckq2A = g_ck + q2A, ckq2B = g_ck + q2B;
    {
        float eA = 0.f, eB = 0.f;
        for (int s = s0A + tid; s < SS; s += NT) {
            float w = 1.0f - (float)(s - s0A) * invlenA;
            float e = expf(tanhf(w * s_sv[0][s] + ckq2A));
            s_c2[0][s] = e * w;
            eA += e;
        }
        for (int s = s0B + tid; s < SS; s += NT) {
            float w = 1.0f - (float)(s - s0B) * invlenB;
            float e = expf(tanhf(w * s_sv[1][s] + ckq2B));
            s_c2[1][s] = e * w;
            eB += e;
        }
#pragma unroll
        for (int o = 16; o; o >>= 1) {
            eA += __shfl_xor_sync(0xffffffffu, eA, o);
            eB += __shfl_xor_sync(0xffffffffu, eB, o);
        }
        if (lane == 0) { s_red[wid][0] = eA; s_red[wid][1] = eB; }
    }
    __syncthreads();
    if (tid == 0) {
        float a = 0.f, c = 0.f;
        for (int w = 0; w < 12; w++) { a += s_red[w][0]; c += s_red[w][1]; }
        s_b[0] = 1.0f / (a + (float)s0A * expf(tanhf(ckq2A)));
        s_b[1] = 1.0f / (c + (float)s0B * expf(tanhf(ckq2B)));
    }
    __syncthreads();
    float inv2A = s_b[0], inv2B = s_b[1];

    // normalize both rows' coefficient sets
    for (int s = s0A + tid; s < SS; s += NT) {
        s_c0[0][s] *= inv0A; s_c1[0][s] *= inv1A; s_c2[0][s] *= inv2A;
    }
    for (int s = s0B + tid; s < SS; s += NT) {
        s_c0[1][s] *= inv0B; s_c1[1][s] *= inv1B; s_c2[1][s] *= inv2B;
    }
    __syncthreads();

    // ---- per-row gather + output (throughput-bound; sequential) ----
#pragma unroll 1
    for (int r = 0; r < 2; r++) {
        int row = r ? rowB : rowA;
        int s0 = r ? s0B : s0A;
        if (tid < 300) {
            int grp = tid / D4;
            int ch = tid - grp * D4;
            float4 a0 = make_float4(0.f, 0.f, 0.f, 0.f);
            float4 a1 = make_float4(0.f, 0.f, 0.f, 0.f);
            float4 a2 = make_float4(0.f, 0.f, 0.f, 0.f);
            int s = s0 + grp;
            for (; s + 28 < SS; s += 32) {
                int ix[8]; float c0[8], c1[8], c2[8];
#pragma unroll
                for (int j = 0; j < 8; j++) {
                    int ss = s + 4 * j;
                    ix[j] = s_idx[r][ss]; c0[j] = s_c0[r][ss];
                    c1[j] = s_c1[r][ss]; c2[j] = s_c2[r][ss];
                }
                uint2 v[8];
#pragma unroll
                for (int j = 0; j < 8; j++) v[j] = g_embh[(size_t)ix[j] * D4 + ch];
#pragma unroll
                for (int j = 0; j < 8; j++) {
                    float2 lo = __half22float2(*reinterpret_cast<__half2*>(&v[j].x));
                    float2 hi = __half22float2(*reinterpret_cast<__half2*>(&v[j].y));
                    a0.x += c0[j] * lo.x; a0.y += c0[j] * lo.y; a0.z += c0[j] * hi.x; a0.w += c0[j] * hi.y;
                    a1.x += c1[j] * lo.x; a1.y += c1[j] * lo.y; a1.z += c1[j] * hi.x; a1.w += c1[j] * hi.y;
                    a2.x += c2[j] * lo.x; a2.y += c2[j] * lo.y; a2.z += c2[j] * hi.x; a2.w += c2[j] * hi.y;
                }
            }
            for (; s < SS; s += 4) {
                float c0 = s_c0[r][s], c1 = s_c1[r][s], c2 = s_c2[r][s];
                uint2 v = g_embh[(size_t)s_idx[r][s] * D4 + ch];
                float2 lo = __half22float2(*reinterpret_cast<__half2*>(&v.x));
                float2 hi = __half22float2(*reinterpret_cast<__half2*>(&v.y));
                a0.x += c0 * lo.x; a0.y += c0 * lo.y; a0.z += c0 * hi.x; a0.w += c0 * hi.y;
                a1.x += c1 * lo.x; a1.y += c1 * lo.y; a1.z += c1 * hi.x; a1.w += c1 * hi.y;
                a2.x += c2 * lo.x; a2.y += c2 * lo.y; a2.z += c2 * hi.x; a2.w += c2 * hi.y;
            }
            s_part[0][grp][ch] = a0;
            s_part[1][grp][ch] = a1;
            s_part[2][grp][ch] = a2;
        }
        __syncthreads();
        // reduce 4 groups into s_part[a][0] (alias "s_am"; read-then-write per thread)
        if (tid < 225) {
            int a = tid / D4, ch = tid - a * D4;
            float4 g0 = s_part[a][0][ch], g1 = s_part[a][1][ch];
            float4 g2 = s_part[a][2][ch], g3 = s_part[a][3][ch];
            float4 rr;
            rr.x = (g0.x + g1.x) + (g2.x + g3.x);
            rr.y = (g0.y + g1.y) + (g2.y + g3.y);
            rr.z = (g0.z + g1.z) + (g2.z + g3.z);
            rr.w = (g0.w + g1.w) + (g2.w + g3.w);
            s_part[a][0][ch] = rr;
        }
        __syncthreads();

        // output: out[row] = M2.am2 + M1.am1 + M0.am0 + Mx.x0 + cvec
        {
            int p = wid >> 2, src = wid & 3;
            const float* M = (src == 0) ? (pM2 + p * DD) : (src == 1) ? (pM1 + p * DD)
                           : (src == 2) ? (pM0 + p * DD) : (pMX + p * DD);
            const float* vec = (src == 3) ? s_x0[r]
                             : reinterpret_cast<const float*>(&s_part[2 - src][0][0]);
            float acc = 0.f;
            for (int d = lane; d < DD; d += 32) acc += M[d] * vec[d];
#pragma unroll
            for (int o = 16; o; o >>= 1) acc += __shfl_xor_sync(0xffffffffu, acc, o);
            if (lane == 0) s_red[wid][0] = acc;
        }
        __syncthreads();
        if (tid < PP) {
            out[row * PP + tid] = pCV[tid] + (s_red[tid * 4][0] + s_red[tid * 4 + 1][0])
                                           + (s_red[tid * 4 + 2][0] + s_red[tid * 4 + 3][0]);
        }
        __syncthreads();
    }
}

// ---------------- launch -----------------
extern "C" void kernel_launch(void* const* d_in, const int* in_sizes, int n_in,
                              void* d_out, int out_size) {
    const int*   text = (const int*)d_in[0];
    const int*   asp  = (const int*)d_in[1];
    const float* emb  = (const float*)d_in[2];
    const float* Wx   = (const float*)d_in[3];
    const float* bx   = (const float*)d_in[4];
    const float* Wk   = (const float*)d_in[5];
    const float* bk   = (const float*)d_in[6];
    const float* Wq   = (const float*)d_in[7];
    const float* bq   = (const float*)d_in[8];
    const float* wmlp = (const float*)d_in[9];
    const float* Wp   = (const float*)d_in[10];
    const float* bp   = (const float*)d_in[11];
    const float* Wd   = (const float*)d_in[12];
    const float* bd   = (const float*)d_in[13];
    float* out = (float*)d_out;

    k_all<<<NBLK, NT>>>(Wq, Wk, Wp, Wx, Wd, wmlp, bk, bq, bp, bx, bd,
                        emb, text, asp, out);
}

// round 14
// speedup vs baseline: 1.4190x; 1.4190x over previous
#include <cuda_runtime.h>
#include <cuda_fp16.h>
#include <math.h>

#define BB 512
#define SS 512
#define VV 50000
#define DD 300
#define PP 3
#define D4 75   // DD/4
#define CE 30   // e per chunk
#define NBLK 256
#define NPREP 71
#define NT 384

// ---------------- accumulator block (zeroed in-kernel) ----------------
#define ACCN 11104
__device__ __align__(16) float g_acc[ACCN];
#define pU   (g_acc + 0)
#define pV   (g_acc + 300)
#define pU2  (g_acc + 600)
#define pB1  (g_acc + 900)
#define pB2  (g_acc + 1200)
#define pP1  (g_acc + 1500)
#define pP2  (g_acc + 1800)
#define pA1  (g_acc + 2100)
#define pA2  (g_acc + 2400)
#define pBCV (g_acc + 2700)
#define pG   (g_acc + 3000)
#define pE   (g_acc + 3900)
#define pH   (g_acc + 4800)
#define pF   (g_acc + 5700)
#define pJ   (g_acc + 6600)
#define pM2  (g_acc + 7500)
#define pM1  (g_acc + 8400)
#define pM0  (g_acc + 9300)
#define pMX  (g_acc + 10200)
#define pCV  (g_acc + 11100)

__device__ float g_ck, g_cq, g_c2, g_cc1, g_cc2;
__device__ __align__(16) float4 g_svt[VV];              // {sv, t1, t2, 0}
__device__ __align__(16) uint2 g_embh[(size_t)VV * D4]; // fp16 emb shadow

// ---------------- replay-safe FLAG-ARRAY grid barrier ----------------
// Each block owns one epoch counter per slot (no atomic contention).
// Block 0 scans all flags in parallel, publishes release epoch.
__device__ volatile int g_flags[8][NBLK];   // zero-init; monotonic epochs
__device__ volatile int g_rel[8];

__device__ __forceinline__ void gridbar(int slot, int count) {
    __syncthreads();
    __shared__ int s_epoch;
    if (threadIdx.x == 0) {
        __threadfence();
        int e = g_flags[slot][blockIdx.x] + 1;
        g_flags[slot][blockIdx.x] = e;
        s_epoch = e;
    }
    __syncthreads();
    int e = s_epoch;
    if (blockIdx.x == 0) {
        for (;;) {
            bool ok = true;
            for (int i = threadIdx.x; i < count; i += NT)
                if (g_flags[slot][i] < e) ok = false;
            if (__syncthreads_and(ok)) break;
            __nanosleep(64);
        }
        if (threadIdx.x == 0) {
            __threadfence();
            g_rel[slot] = e;
        }
        __syncthreads();
    } else {
        if (threadIdx.x == 0) {
            while (g_rel[slot] < e) __nanosleep(64);
            __threadfence();
        }
        __syncthreads();
    }
}

// ---------------- device helpers ----------------
__device__ __forceinline__ float lanedot(const float* __restrict__ a,
                                         const float* __restrict__ b, int lane) {
    float s = 0.f;
    for (int e = lane; e < DD; e += 32) s += a[e] * b[e];
#pragma unroll
    for (int o = 16; o; o >>= 1) s += __shfl_xor_sync(0xffffffffu, s, o);
    return s;
}

// out[f] += sum_{e in chunk} M[e*DD+f] * y[e]
__device__ __forceinline__ void mv_part(const float* __restrict__ M,
                                        const float* __restrict__ y,
                                        float* __restrict__ out, int chunk) {
    __shared__ float sy[CE];
    int t = threadIdx.x;
    if (t < CE) sy[t] = y[chunk * CE + t];
    __syncthreads();
    if (t < DD) {
        float acc = 0.f;
        const float* Mp = M + chunk * CE * DD + t;
#pragma unroll
        for (int e = 0; e < CE; e++) acc += Mp[e * DD] * sy[e];
        atomicAdd(out + t, acc);
    }
    __syncthreads();
}

// out[p][f] += sum_{e in chunk} A[p*DD+e] * B[e*DD+f]  for p=0..2
__device__ __forceinline__ void mm3_part(const float* __restrict__ A,
                                         const float* __restrict__ B,
                                         float* __restrict__ out, int chunk) {
    __shared__ float sa[3][CE];
    int t = threadIdx.x;
    if (t < 3 * CE) sa[t / CE][t % CE] = A[(t / CE) * DD + chunk * CE + (t % CE)];
    __syncthreads();
    if (t < DD) {
        float a0 = 0.f, a1 = 0.f, a2 = 0.f;
        const float* Bp = B + chunk * CE * DD + t;
#pragma unroll
        for (int e = 0; e < CE; e++) {
            float b = Bp[e * DD];
            a0 += sa[0][e] * b; a1 += sa[1][e] * b; a2 += sa[2][e] * b;
        }
        atomicAdd(out + t, a0);
        atomicAdd(out + DD + t, a1);
        atomicAdd(out + 2 * DD + t, a2);
    }
    __syncthreads();
}

// ============================================================
// ONE persistent kernel: prep chain || shadow build, then svt, then mega.
// ============================================================
__global__ __launch_bounds__(NT, 2) void k_all(
        const float* __restrict__ Wq, const float* __restrict__ Wk,
        const float* __restrict__ Wp, const float* __restrict__ Wx,
        const float* __restrict__ Wd, const float* __restrict__ wmlp,
        const float* __restrict__ bk, const float* __restrict__ bq,
        const float* __restrict__ bp, const float* __restrict__ bx,
        const float* __restrict__ bd, const float* __restrict__ emb,
        const int* __restrict__ text, const int* __restrict__ asp,
        float* __restrict__ out) {
    int b = blockIdx.x, tid = threadIdx.x;
    int lane = tid & 31, wid = tid >> 5;

    // shared memory
    __shared__ int   s_idx[SS];
    __shared__ int   s_asp[8];
    __shared__ int   s_len;
    __shared__ float s_sv[SS], s_t1[SS], s_t2[SS];
    __shared__ float s_c0[SS], s_c1[SS], s_c2[SS];
    __shared__ __align__(16) float s_x0[DD];
    __shared__ __align__(16) float4 s_part[3][4][D4];
    __shared__ __align__(16) float s_am[3][DD];
    __shared__ float s_red[12][3];
    __shared__ float s_b[6];
    __shared__ __align__(16) float4 sV[D4], sA1[D4], sA2[D4];

    // ================= phase A: prep chain (blocks < NPREP) or shadow =======
    if (b < NPREP) {
        // level 0: zero accumulators
        for (int i = b * NT + tid; i < ACCN; i += NPREP * NT) g_acc[i] = 0.f;
        gridbar(0, NPREP);

        // level 1: u, v, G, E, bcv, ck/cq
        if (b < 10) {
            mv_part(Wq, wmlp + DD, pU, b);
        } else if (b < 20) {
            mv_part(Wk, wmlp, pV, b - 10);
        } else if (b < 30) {
            mm3_part(Wd, Wp, pG, b - 20);
        } else if (b < 40) {
            mm3_part(Wd, Wx, pE, b - 30);
        } else if (b < 70) {
            if (wid < 10) {
                int row = (b - 40) * 10 + wid;
                float s = lanedot(Wp + row * DD, bk, lane);
                if (lane == 0) pBCV[row] = s + bp[row] + bx[row];
            }
        } else {
            if (wid == 0) { float s = lanedot(bk, wmlp, lane); if (lane == 0) g_ck = s; }
            if (wid == 1) { float s = lanedot(bq, wmlp + DD, lane); if (lane == 0) g_cq = s; }
        }
        gridbar(1, NPREP);

        // level 2: u2, M2, H, F, c2
        if (b < 10) {
            mv_part(Wx, pU, pU2, b);
        } else if (b < 20) {
            mm3_part(pG, Wk, pM2, b - 10);
        } else if (b < 30) {
            mm3_part(pE, Wp, pH, b - 20);
        } else if (b < 40) {
            mm3_part(pE, Wx, pF, b - 30);
        } else if (b == 40) {
            if (wid == 0) { float s = lanedot(bx, pU, lane); if (lane == 0) g_c2 = s + g_cq; }
        }
        gridbar(2, NPREP);

        // level 3: b1, p1, M1, Mx, J, cc1, cvec
        if (b < 10) {
            mv_part(Wx, pU2, pB1, b);
        } else if (b < 20) {
            mv_part(Wp, pU2, pP1, b - 10);
        } else if (b < 30) {
            mm3_part(pH, Wk, pM1, b - 20);
        } else if (b < 40) {
            mm3_part(pF, Wx, pMX, b - 30);
        } else if (b < 50) {
            mm3_part(pF, Wp, pJ, b - 40);
        } else if (b == 50) {
            if (wid == 0) { float s = lanedot(pBCV, pU2, lane); if (lane == 0) s_b[0] = s; }
            if (wid >= 1 && wid <= 3) {
                int p = wid - 1;
                float s = 0.f;
                for (int e = lane; e < DD; e += 32)
                    s += (Wd[p * DD + e] + pE[p * DD + e] + pF[p * DD + e]) * pBCV[e];
#pragma unroll
                for (int o = 16; o; o >>= 1) s += __shfl_xor_sync(0xffffffffu, s, o);
                if (lane == 0) pCV[p] = s + bd[p];
            }
            __syncthreads();
            if (tid == 0) g_cc1 = s_b[0] + g_c2;
            __syncthreads();
        }
        gridbar(3, NPREP);

        // level 4: a1, b2, p2, M0, cc2
        if (b < 10) {
            mv_part(Wk, pP1, pA1, b);
        } else if (b < 20) {
            mv_part(Wx, pB1, pB2, b - 10);
        } else if (b < 30) {
            mv_part(Wp, pB1, pP2, b - 20);
        } else if (b < 40) {
            mm3_part(pJ, Wk, pM0, b - 30);
        } else if (b == 40) {
            if (wid == 0) { float s = lanedot(pBCV, pB1, lane); if (lane == 0) g_cc2 = s + g_cc1; }
        }
        gridbar(4, NPREP);

        // level 5: a2
        if (b < 10) mv_part(Wk, pP2, pA2, b);
    } else {
        // ---- fp16 shadow: flat coalesced convert, manual x4 MLP ----
        const int TOT = VV * D4;
        const int NSH = (NBLK - NPREP) * NT;
        const float4* em4 = reinterpret_cast<const float4*>(emb);
        int c = (b - NPREP) * NT + tid;
        for (; c + 3 * NSH < TOT; c += 4 * NSH) {
            float4 e0 = em4[c], e1 = em4[c + NSH], e2 = em4[c + 2 * NSH], e3 = em4[c + 3 * NSH];
            uint2 u0, u1, u2, u3;
            __half2 h;
            h = __floats2half2_rn(e0.x, e0.y); u0.x = *reinterpret_cast<unsigned*>(&h);
            h = __floats2half2_rn(e0.z, e0.w); u0.y = *reinterpret_cast<unsigned*>(&h);
            h = __floats2half2_rn(e1.x, e1.y); u1.x = *reinterpret_cast<unsigned*>(&h);
            h = __floats2half2_rn(e1.z, e1.w); u1.y = *reinterpret_cast<unsigned*>(&h);
            h = __floats2half2_rn(e2.x, e2.y); u2.x = *reinterpret_cast<unsigned*>(&h);
            h = __floats2half2_rn(e2.z, e2.w); u2.y = *reinterpret_cast<unsigned*>(&h);
            h = __floats2half2_rn(e3.x, e3.y); u3.x = *reinterpret_cast<unsigned*>(&h);
            h = __floats2half2_rn(e3.z, e3.w); u3.y = *reinterpret_cast<unsigned*>(&h);
            g_embh[c] = u0; g_embh[c + NSH] = u1;
            g_embh[c + 2 * NSH] = u2; g_embh[c + 3 * NSH] = u3;
        }
        for (; c < TOT; c += NSH) {
            float4 e = em4[c];
            uint2 u; __half2 h;
            h = __floats2half2_rn(e.x, e.y); u.x = *reinterpret_cast<unsigned*>(&h);
            h = __floats2half2_rn(e.z, e.w); u.y = *reinterpret_cast<unsigned*>(&h);
            g_embh[c] = u;
        }
    }
    gridbar(5, NBLK);

    // ================= phase B: svt from fp16 shadow ========================
    if (tid < D4) {
        sV[tid]  = reinterpret_cast<const float4*>(pV)[tid];
        sA1[tid] = reinterpret_cast<const float4*>(pA1)[tid];
        sA2[tid] = reinterpret_cast<const float4*>(pA2)[tid];
    }
    __syncthreads();
    for (int row = b * 12 + wid; row < VV; row += NBLK * 12) {
        const uint2* er = g_embh + (size_t)row * D4;
        float av = 0.f, a1 = 0.f, a2 = 0.f;
#pragma unroll
        for (int i = lane; i < D4; i += 32) {
            uint2 u = er[i];
            float2 lo = __half22float2(*reinterpret_cast<__half2*>(&u.x));
            float2 hi = __half22float2(*reinterpret_cast<__half2*>(&u.y));
            float4 vv = sV[i], w1 = sA1[i], w2 = sA2[i];
            av += lo.x * vv.x + lo.y * vv.y + hi.x * vv.z + hi.y * vv.w;
            a1 += lo.x * w1.x + lo.y * w1.y + hi.x * w1.z + hi.y * w1.w;
            a2 += lo.x * w2.x + lo.y * w2.y + hi.x * w2.z + hi.y * w2.w;
        }
#pragma unroll
        for (int o = 16; o; o >>= 1) {
            av += __shfl_xor_sync(0xffffffffu, av, o);
            a1 += __shfl_xor_sync(0xffffffffu, a1, o);
            a2 += __shfl_xor_sync(0xffffffffu, a2, o);
        }
        if (lane == 0) g_svt[row] = make_float4(av, a1, a2, 0.f);
    }
    gridbar(6, NBLK);

    // ================= phase C: mega ========================
    for (int row = b; row < BB; row += NBLK) {
        if (tid < 8) s_asp[tid] = asp[row * 8 + tid];
        int cnt = 0;
        for (int s = tid; s < SS; s += NT) {
            int ix = text[row * SS + s];
            s_idx[s] = ix;
            cnt += (ix != 0);
            float4 svt = g_svt[ix];
            s_sv[s] = svt.x; s_t1[s] = svt.y; s_t2[s] = svt.z;
        }
#pragma unroll
        for (int o = 16; o; o >>= 1) cnt += __shfl_xor_sync(0xffffffffu, cnt, o);
        if (lane == 0) s_red[wid][0] = (float)cnt;
        __syncthreads();
        if (tid == 0) {
            float a = 0.f;
            for (int w = 0; w < 12; w++) a += s_red[w][0];
            s_len = (int)a;
        }
        // x0 from fp16 shadow
        if (tid < D4) {
            int na = 0;
#pragma unroll
            for (int j = 0; j < 8; j++) na += (s_asp[j] != 0);
            float invn = 1.0f / (float)na;
            float4 acc = make_float4(0.f, 0.f, 0.f, 0.f);
#pragma unroll
            for (int j = 0; j < 8; j++) {
                uint2 v = g_embh[(size_t)s_asp[j] * D4 + tid];   // row 0 is zeros
                float2 lo = __half22float2(*reinterpret_cast<__half2*>(&v.x));
                float2 hi = __half22float2(*reinterpret_cast<__half2*>(&v.y));
                acc.x += lo.x; acc.y += lo.y; acc.z += hi.x; acc.w += hi.y;
            }
            acc.x *= invn; acc.y *= invn; acc.z *= invn; acc.w *= invn;
            reinterpret_cast<float4*>(s_x0)[tid] = acc;
        }
        __syncthreads();

        float d0 = 0.f, d1 = 0.f, d2 = 0.f;
        if (tid < DD) {
            float xv = s_x0[tid];
            d0 = xv * pU2[tid]; d1 = xv * pB1[tid]; d2 = xv * pB2[tid];
        }
#pragma unroll
        for (int o = 16; o; o >>= 1) {
            d0 += __shfl_xor_sync(0xffffffffu, d0, o);
            d1 += __shfl_xor_sync(0xffffffffu, d1, o);
            d2 += __shfl_xor_sync(0xffffffffu, d2, o);
        }
        if (lane == 0) { s_red[wid][0] = d0; s_red[wid][1] = d1; s_red[wid][2] = d2; }
        __syncthreads();
        if (tid == 0) {
            float a = 0.f, c = 0.f, e = 0.f;
            for (int w = 0; w < 12; w++) { a += s_red[w][0]; c += s_red[w][1]; e += s_red[w][2]; }
            s_b[0] = a; s_b[1] = c; s_b[2] = e;
        }
        __syncthreads();
        float du2 = s_b[0], db1 = s_b[1], db2 = s_b[2];

        int len = s_len;
        int s0 = SS - len;
        float invlen = 1.0f / (float)len;

        // hop 0
        float ckq0 = g_ck + du2 + g_c2;
        float es = 0.f, S01 = 0.f, S02 = 0.f;
        for (int s = s0 + tid; s < SS; s += NT) {
            float w = 1.0f - (float)(s - s0) * invlen;
            float e = expf(tanhf(w * s_sv[s] + ckq0));
            float ew = e * w;
            s_c0[s] = ew;
            es += e; S01 += ew * s_t1[s]; S02 += ew * s_t2[s];
        }
#pragma unroll
        for (int o = 16; o; o >>= 1) {
            es  += __shfl_xor_sync(0xffffffffu, es, o);
            S01 += __shfl_xor_sync(0xffffffffu, S01, o);
            S02 += __shfl_xor_sync(0xffffffffu, S02, o);
        }
        if (lane == 0) { s_red[wid][0] = es; s_red[wid][1] = S01; s_red[wid][2] = S02; }
        __syncthreads();
        if (tid == 0) {
            float a = 0.f, c = 0.f, e = 0.f;
            for (int w = 0; w < 12; w++) { a += s_red[w][0]; c += s_red[w][1]; e += s_red[w][2]; }
            float inv0 = 1.0f / (a + (float)s0 * expf(tanhf(ckq0)));
            s_b[0] = inv0;
            s_b[1] = inv0 * c;
            s_b[2] = inv0 * e;
        }
        __syncthreads();
        float inv0 = s_b[0];
        float q1 = s_b[1] + db1 + g_cc1;

        // hop 1
        float ckq1 = g_ck + q1;
        es = 0.f; S01 = 0.f;
        for (int s = s0 + tid; s < SS; s += NT) {
            float w = 1.0f - (float)(s - s0) * invlen;
            float e = expf(tanhf(w * s_sv[s] + ckq1));
            float ew = e * w;
            s_c1[s] = ew;
            es += e; S01 += ew * s_t1[s];
        }
#pragma unroll
        for (int o = 16; o; o >>= 1) {
            es  += __shfl_xor_sync(0xffffffffu, es, o);
            S01 += __shfl_xor_sync(0xffffffffu, S01, o);
        }
        if (lane == 0) { s_red[wid][0] = es; s_red[wid][1] = S01; }
        __syncthreads();
        if (tid == 0) {
            float a = 0.f, c = 0.f;
            for (int w = 0; w < 12; w++) { a += s_red[w][0]; c += s_red[w][1]; }
            float inv1 = 1.0f / (a + (float)s0 * expf(tanhf(ckq1)));
            s_b[3] = inv1;
            s_b[4] = inv1 * c;
        }
        __syncthreads();
        float inv1 = s_b[3];
        float q2 = s_b[4] + s_b[2] + db2 + g_cc2;

        // hop 2
        float ckq2 = g_ck + q2;
        es = 0.f;
        for (int s = s0 + tid; s < SS; s += NT) {
            float w = 1.0f - (float)(s - s0) * invlen;
            float e = expf(tanhf(w * s_sv[s] + ckq2));
            s_c2[s] = e * w;
            es += e;
        }
#pragma unroll
        for (int o = 16; o; o >>= 1) es += __shfl_xor_sync(0xffffffffu, es, o);
        if (lane == 0) s_red[wid][0] = es;
        __syncthreads();
        if (tid == 0) {
            float a = 0.f;
            for (int w = 0; w < 12; w++) a += s_red[w][0];
            s_b[5] = 1.0f / (a + (float)s0 * expf(tanhf(ckq2)));
        }
        __syncthreads();
        float inv2 = s_b[5];

        for (int s = s0 + tid; s < SS; s += NT) {
            s_c0[s] *= inv0; s_c1[s] *= inv1; s_c2[s] *= inv2;
        }
        __syncthreads();

        // single shared gather: am0, am1, am2
        if (tid < 300) {
            int grp = tid / D4;
            int ch = tid - grp * D4;
            float4 a0 = make_float4(0.f, 0.f, 0.f, 0.f);
            float4 a1 = make_float4(0.f, 0.f, 0.f, 0.f);
            float4 a2 = make_float4(0.f, 0.f, 0.f, 0.f);
            int s = s0 + grp;
            for (; s + 28 < SS; s += 32) {
                int ix[8]; float c0[8], c1[8], c2[8];
#pragma unroll
                for (int j = 0; j < 8; j++) {
                    int ss = s + 4 * j;
                    ix[j] = s_idx[ss]; c0[j] = s_c0[ss]; c1[j] = s_c1[ss]; c2[j] = s_c2[ss];
                }
                uint2 v[8];
#pragma unroll
                for (int j = 0; j < 8; j++) v[j] = g_embh[(size_t)ix[j] * D4 + ch];
#pragma unroll
                for (int j = 0; j < 8; j++) {
                    float2 lo = __half22float2(*reinterpret_cast<__half2*>(&v[j].x));
                    float2 hi = __half22float2(*reinterpret_cast<__half2*>(&v[j].y));
                    a0.x += c0[j] * lo.x; a0.y += c0[j] * lo.y; a0.z += c0[j] * hi.x; a0.w += c0[j] * hi.y;
                    a1.x += c1[j] * lo.x; a1.y += c1[j] * lo.y; a1.z += c1[j] * hi.x; a1.w += c1[j] * hi.y;
                    a2.x += c2[j] * lo.x; a2.y += c2[j] * lo.y; a2.z += c2[j] * hi.x; a2.w += c2[j] * hi.y;
                }
            }
            for (; s < SS; s += 4) {
                float c0 = s_c0[s], c1 = s_c1[s], c2 = s_c2[s];
                uint2 v = g_embh[(size_t)s_idx[s] * D4 + ch];
                float2 lo = __half22float2(*reinterpret_cast<__half2*>(&v.x));
                float2 hi = __half22float2(*reinterpret_cast<__half2*>(&v.y));
                a0.x += c0 * lo.x; a0.y += c0 * lo.y; a0.z += c0 * hi.x; a0.w += c0 * hi.y;
                a1.x += c1 * lo.x; a1.y += c1 * lo.y; a1.z += c1 * hi.x; a1.w += c1 * hi.y;
                a2.x += c2 * lo.x; a2.y += c2 * lo.y; a2.z += c2 * hi.x; a2.w += c2 * hi.y;
            }
            s_part[0][grp][ch] = a0;
            s_part[1][grp][ch] = a1;
            s_part[2][grp][ch] = a2;
        }
        __syncthreads();
        if (tid < 225) {
            int a = tid / D4, ch = tid - a * D4;
            float4 g0 = s_part[a][0][ch], g1 = s_part[a][1][ch];
            float4 g2 = s_part[a][2][ch], g3 = s_part[a][3][ch];
            float4 r;
            r.x = (g0.x + g1.x) + (g2.x + g3.x);
            r.y = (g0.y + g1.y) + (g2.y + g3.y);
            r.z = (g0.z + g1.z) + (g2.z + g3.z);
            r.w = (g0.w + g1.w) + (g2.w + g3.w);
            reinterpret_cast<float4*>(s_am[a])[ch] = r;
        }
        __syncthreads();

        // output: out[row] = M2.am2 + M1.am1 + M0.am0 + Mx.x0 + cvec
        {
            int p = wid >> 2, src = wid & 3;
            const float* M = (src == 0) ? (pM2 + p * DD) : (src == 1) ? (pM1 + p * DD)
                           : (src == 2) ? (pM0 + p * DD) : (pMX + p * DD);
            const float* vec = (src == 0) ? s_am[2] : (src == 1) ? s_am[1]
                             : (src == 2) ? s_am[0] : s_x0;
            float acc = 0.f;
            for (int d = lane; d < DD; d += 32) acc += M[d] * vec[d];
#pragma unroll
            for (int o = 16; o; o >>= 1) acc += __shfl_xor_sync(0xffffffffu, acc, o);
            if (lane == 0) s_red[wid][0] = acc;
        }
        __syncthreads();
        if (tid < PP) {
            out[row * PP + tid] = pCV[tid] + (s_red[tid * 4][0] + s_red[tid * 4 + 1][0])
                                           + (s_red[tid * 4 + 2][0] + s_red[tid * 4 + 3][0]);
        }
        __syncthreads();
    }
}

// ---------------- launch -----------------
extern "C" void kernel_launch(void* const* d_in, const int* in_sizes, int n_in,
                              void* d_out, int out_size) {
    const int*   text = (const int*)d_in[0];
    const int*   asp  = (const int*)d_in[1];
    const float* emb  = (const float*)d_in[2];
    const float* Wx   = (const float*)d_in[3];
    const float* bx   = (const float*)d_in[4];
    const float* Wk   = (const float*)d_in[5];
    const float* bk   = (const float*)d_in[6];
    const float* Wq   = (const float*)d_in[7];
    const float* bq   = (const float*)d_in[8];
    const float* wmlp = (const float*)d_in[9];
    const float* Wp   = (const float*)d_in[10];
    const float* bp   = (const float*)d_in[11];
    const float* Wd   = (const float*)d_in[12];
    const float* bd   = (const float*)d_in[13];
    float* out = (float*)d_out;

    k_all<<<NBLK, NT>>>(Wq, Wk, Wp, Wx, Wd, wmlp, bk, bq, bp, bx, bd,
                        emb, text, asp, out);
}

// round 15
// speedup vs baseline: 1.5212x; 1.0720x over previous
#include <cuda_runtime.h>
#include <cuda_fp16.h>
#include <math.h>

#define BB 512
#define SS 512
#define VV 50000
#define DD 300
#define PP 3
#define D4 75   // DD/4
#define CE 30   // e per chunk
#define NBLK 444
#define NPREP 71
#define NT 384

// ---------------- accumulator block (zeroed in-kernel) ----------------
#define ACCN 11104
__device__ __align__(16) float g_acc[ACCN];
#define pU   (g_acc + 0)
#define pV   (g_acc + 300)
#define pU2  (g_acc + 600)
#define pB1  (g_acc + 900)
#define pB2  (g_acc + 1200)
#define pP1  (g_acc + 1500)
#define pP2  (g_acc + 1800)
#define pA1  (g_acc + 2100)
#define pA2  (g_acc + 2400)
#define pBCV (g_acc + 2700)
#define pG   (g_acc + 3000)
#define pE   (g_acc + 3900)
#define pH   (g_acc + 4800)
#define pF   (g_acc + 5700)
#define pJ   (g_acc + 6600)
#define pM2  (g_acc + 7500)
#define pM1  (g_acc + 8400)
#define pM0  (g_acc + 9300)
#define pMX  (g_acc + 10200)
#define pCV  (g_acc + 11100)

__device__ float g_ck, g_cq, g_c2, g_cc1, g_cc2;
__device__ __align__(16) float4 g_svt[VV];              // {sv, t1, t2, 0}
__device__ __align__(16) uint2 g_embh[(size_t)VV * D4]; // fp16 emb shadow

// ---------------- replay-safe grid barrier (atomic counter; R10-proven) -----
__device__ volatile unsigned g_barphase[8];
__device__ unsigned g_barcnt[8];

__device__ __forceinline__ void gridbar(int slot, unsigned count) {
    __syncthreads();
    if (threadIdx.x == 0) {
        __threadfence();
        unsigned ph = g_barphase[slot];
        unsigned t = atomicAdd(&g_barcnt[slot], 1u);
        if (t == count - 1) {
            g_barcnt[slot] = 0;            // reset for next replay
            __threadfence();
            atomicAdd((unsigned*)&g_barphase[slot], 1u);
        } else {
            while (g_barphase[slot] == ph) { __nanosleep(32); }
        }
        __threadfence();
    }
    __syncthreads();
}

// ---------------- device helpers ----------------
__device__ __forceinline__ float lanedot(const float* __restrict__ a,
                                         const float* __restrict__ b, int lane) {
    float s = 0.f;
    for (int e = lane; e < DD; e += 32) s += a[e] * b[e];
#pragma unroll
    for (int o = 16; o; o >>= 1) s += __shfl_xor_sync(0xffffffffu, s, o);
    return s;
}

// out[f] += sum_{e in chunk} M[e*DD+f] * y[e]
__device__ __forceinline__ void mv_part(const float* __restrict__ M,
                                        const float* __restrict__ y,
                                        float* __restrict__ out, int chunk) {
    __shared__ float sy[CE];
    int t = threadIdx.x;
    if (t < CE) sy[t] = y[chunk * CE + t];
    __syncthreads();
    if (t < DD) {
        float acc = 0.f;
        const float* Mp = M + chunk * CE * DD + t;
#pragma unroll
        for (int e = 0; e < CE; e++) acc += Mp[e * DD] * sy[e];
        atomicAdd(out + t, acc);
    }
    __syncthreads();
}

// out[p][f] += sum_{e in chunk} A[p*DD+e] * B[e*DD+f]  for p=0..2
__device__ __forceinline__ void mm3_part(const float* __restrict__ A,
                                         const float* __restrict__ B,
                                         float* __restrict__ out, int chunk) {
    __shared__ float sa[3][CE];
    int t = threadIdx.x;
    if (t < 3 * CE) sa[t / CE][t % CE] = A[(t / CE) * DD + chunk * CE + (t % CE)];
    __syncthreads();
    if (t < DD) {
        float a0 = 0.f, a1 = 0.f, a2 = 0.f;
        const float* Bp = B + chunk * CE * DD + t;
#pragma unroll
        for (int e = 0; e < CE; e++) {
            float b = Bp[e * DD];
            a0 += sa[0][e] * b; a1 += sa[1][e] * b; a2 += sa[2][e] * b;
        }
        atomicAdd(out + t, a0);
        atomicAdd(out + DD + t, a1);
        atomicAdd(out + 2 * DD + t, a2);
    }
    __syncthreads();
}

// ============================================================
// ONE persistent kernel: prep chain || shadow build, then svt, then mega.
// 3 CTAs/SM (NBLK = 148*3 = 444, one wave).
// ============================================================
__global__ __launch_bounds__(NT, 3) void k_all(
        const float* __restrict__ Wq, const float* __restrict__ Wk,
        const float* __restrict__ Wp, const float* __restrict__ Wx,
        const float* __restrict__ Wd, const float* __restrict__ wmlp,
        const float* __restrict__ bk, const float* __restrict__ bq,
        const float* __restrict__ bp, const float* __restrict__ bx,
        const float* __restrict__ bd, const float* __restrict__ emb,
        const int* __restrict__ text, const int* __restrict__ asp,
        float* __restrict__ out) {
    int b = blockIdx.x, tid = threadIdx.x;
    int lane = tid & 31, wid = tid >> 5;

    // shared memory
    __shared__ int   s_idx[SS];
    __shared__ int   s_asp[8];
    __shared__ int   s_len;
    __shared__ float s_sv[SS], s_t1[SS], s_t2[SS];
    __shared__ float s_c0[SS], s_c1[SS], s_c2[SS];
    __shared__ __align__(16) float s_x0[DD];
    __shared__ __align__(16) float4 s_part[3][4][D4];
    __shared__ __align__(16) float s_am[3][DD];
    __shared__ float s_red[12][3];
    __shared__ float s_b[6];
    __shared__ __align__(16) float4 sV[D4], sA1[D4], sA2[D4];

    // ================= phase A: prep chain (blocks < NPREP) or shadow =======
    if (b < NPREP) {
        for (int i = b * NT + tid; i < ACCN; i += NPREP * NT) g_acc[i] = 0.f;
        gridbar(0, NPREP);

        // level 1: u, v, G, E, bcv, ck/cq
        if (b < 10) {
            mv_part(Wq, wmlp + DD, pU, b);
        } else if (b < 20) {
            mv_part(Wk, wmlp, pV, b - 10);
        } else if (b < 30) {
            mm3_part(Wd, Wp, pG, b - 20);
        } else if (b < 40) {
            mm3_part(Wd, Wx, pE, b - 30);
        } else if (b < 70) {
            if (wid < 10) {
                int row = (b - 40) * 10 + wid;
                float s = lanedot(Wp + row * DD, bk, lane);
                if (lane == 0) pBCV[row] = s + bp[row] + bx[row];
            }
        } else {
            if (wid == 0) { float s = lanedot(bk, wmlp, lane); if (lane == 0) g_ck = s; }
            if (wid == 1) { float s = lanedot(bq, wmlp + DD, lane); if (lane == 0) g_cq = s; }
        }
        gridbar(1, NPREP);

        // level 2: u2, M2, H, F, c2
        if (b < 10) {
            mv_part(Wx, pU, pU2, b);
        } else if (b < 20) {
            mm3_part(pG, Wk, pM2, b - 10);
        } else if (b < 30) {
            mm3_part(pE, Wp, pH, b - 20);
        } else if (b < 40) {
            mm3_part(pE, Wx, pF, b - 30);
        } else if (b == 40) {
            if (wid == 0) { float s = lanedot(bx, pU, lane); if (lane == 0) g_c2 = s + g_cq; }
        }
        gridbar(2, NPREP);

        // level 3: b1, p1, M1, Mx, J, cc1, cvec
        if (b < 10) {
            mv_part(Wx, pU2, pB1, b);
        } else if (b < 20) {
            mv_part(Wp, pU2, pP1, b - 10);
        } else if (b < 30) {
            mm3_part(pH, Wk, pM1, b - 20);
        } else if (b < 40) {
            mm3_part(pF, Wx, pMX, b - 30);
        } else if (b < 50) {
            mm3_part(pF, Wp, pJ, b - 40);
        } else if (b == 50) {
            if (wid == 0) { float s = lanedot(pBCV, pU2, lane); if (lane == 0) s_b[0] = s; }
            if (wid >= 1 && wid <= 3) {
                int p = wid - 1;
                float s = 0.f;
                for (int e = lane; e < DD; e += 32)
                    s += (Wd[p * DD + e] + pE[p * DD + e] + pF[p * DD + e]) * pBCV[e];
#pragma unroll
                for (int o = 16; o; o >>= 1) s += __shfl_xor_sync(0xffffffffu, s, o);
                if (lane == 0) pCV[p] = s + bd[p];
            }
            __syncthreads();
            if (tid == 0) g_cc1 = s_b[0] + g_c2;
            __syncthreads();
        }
        gridbar(3, NPREP);

        // level 4: a1, b2, p2, M0, cc2
        if (b < 10) {
            mv_part(Wk, pP1, pA1, b);
        } else if (b < 20) {
            mv_part(Wx, pB1, pB2, b - 10);
        } else if (b < 30) {
            mv_part(Wp, pB1, pP2, b - 20);
        } else if (b < 40) {
            mm3_part(pJ, Wk, pM0, b - 30);
        } else if (b == 40) {
            if (wid == 0) { float s = lanedot(pBCV, pB1, lane); if (lane == 0) g_cc2 = s + g_cc1; }
        }
        gridbar(4, NPREP);

        // level 5: a2
        if (b < 10) mv_part(Wk, pP2, pA2, b);
    } else {
        // ---- fp16 shadow: flat coalesced convert, manual x4 MLP ----
        const int TOT = VV * D4;
        const int NSH = (NBLK - NPREP) * NT;
        const float4* em4 = reinterpret_cast<const float4*>(emb);
        int c = (b - NPREP) * NT + tid;
        for (; c + 3 * NSH < TOT; c += 4 * NSH) {
            float4 e0 = em4[c], e1 = em4[c + NSH], e2 = em4[c + 2 * NSH], e3 = em4[c + 3 * NSH];
            uint2 u0, u1, u2, u3;
            __half2 h;
            h = __floats2half2_rn(e0.x, e0.y); u0.x = *reinterpret_cast<unsigned*>(&h);
            h = __floats2half2_rn(e0.z, e0.w); u0.y = *reinterpret_cast<unsigned*>(&h);
            h = __floats2half2_rn(e1.x, e1.y); u1.x = *reinterpret_cast<unsigned*>(&h);
            h = __floats2half2_rn(e1.z, e1.w); u1.y = *reinterpret_cast<unsigned*>(&h);
            h = __floats2half2_rn(e2.x, e2.y); u2.x = *reinterpret_cast<unsigned*>(&h);
            h = __floats2half2_rn(e2.z, e2.w); u2.y = *reinterpret_cast<unsigned*>(&h);
            h = __floats2half2_rn(e3.x, e3.y); u3.x = *reinterpret_cast<unsigned*>(&h);
            h = __floats2half2_rn(e3.z, e3.w); u3.y = *reinterpret_cast<unsigned*>(&h);
            g_embh[c] = u0; g_embh[c + NSH] = u1;
            g_embh[c + 2 * NSH] = u2; g_embh[c + 3 * NSH] = u3;
        }
        for (; c < TOT; c += NSH) {
            float4 e = em4[c];
            uint2 u; __half2 h;
            h = __floats2half2_rn(e.x, e.y); u.x = *reinterpret_cast<unsigned*>(&h);
            h = __floats2half2_rn(e.z, e.w); u.y = *reinterpret_cast<unsigned*>(&h);
            g_embh[c] = u;
        }
    }
    gridbar(5, NBLK);

    // ================= phase B: svt from fp16 shadow ========================
    if (tid < D4) {
        sV[tid]  = reinterpret_cast<const float4*>(pV)[tid];
        sA1[tid] = reinterpret_cast<const float4*>(pA1)[tid];
        sA2[tid] = reinterpret_cast<const float4*>(pA2)[tid];
    }
    __syncthreads();
    for (int row = b * 12 + wid; row < VV; row += NBLK * 12) {
        const uint2* er = g_embh + (size_t)row * D4;
        float av = 0.f, a1 = 0.f, a2 = 0.f;
#pragma unroll
        for (int i = lane; i < D4; i += 32) {
            uint2 u = er[i];
            float2 lo = __half22float2(*reinterpret_cast<__half2*>(&u.x));
            float2 hi = __half22float2(*reinterpret_cast<__half2*>(&u.y));
            float4 vv = sV[i], w1 = sA1[i], w2 = sA2[i];
            av += lo.x * vv.x + lo.y * vv.y + hi.x * vv.z + hi.y * vv.w;
            a1 += lo.x * w1.x + lo.y * w1.y + hi.x * w1.z + hi.y * w1.w;
            a2 += lo.x * w2.x + lo.y * w2.y + hi.x * w2.z + hi.y * w2.w;
        }
#pragma unroll
        for (int o = 16; o; o >>= 1) {
            av += __shfl_xor_sync(0xffffffffu, av, o);
            a1 += __shfl_xor_sync(0xffffffffu, a1, o);
            a2 += __shfl_xor_sync(0xffffffffu, a2, o);
        }
        if (lane == 0) g_svt[row] = make_float4(av, a1, a2, 0.f);
    }
    gridbar(6, NBLK);

    // ================= phase C: mega ========================
    for (int row = b; row < BB; row += NBLK) {
        if (tid < 8) s_asp[tid] = asp[row * 8 + tid];
        int cnt = 0;
        for (int s = tid; s < SS; s += NT) {
            int ix = text[row * SS + s];
            s_idx[s] = ix;
            cnt += (ix != 0);
            float4 svt = g_svt[ix];
            s_sv[s] = svt.x; s_t1[s] = svt.y; s_t2[s] = svt.z;
        }
#pragma unroll
        for (int o = 16; o; o >>= 1) cnt += __shfl_xor_sync(0xffffffffu, cnt, o);
        if (lane == 0) s_red[wid][0] = (float)cnt;
        __syncthreads();
        if (tid == 0) {
            float a = 0.f;
            for (int w = 0; w < 12; w++) a += s_red[w][0];
            s_len = (int)a;
        }
        // x0 from fp16 shadow
        if (tid < D4) {
            int na = 0;
#pragma unroll
            for (int j = 0; j < 8; j++) na += (s_asp[j] != 0);
            float invn = 1.0f / (float)na;
            float4 acc = make_float4(0.f, 0.f, 0.f, 0.f);
#pragma unroll
            for (int j = 0; j < 8; j++) {
                uint2 v = g_embh[(size_t)s_asp[j] * D4 + tid];   // row 0 is zeros
                float2 lo = __half22float2(*reinterpret_cast<__half2*>(&v.x));
                float2 hi = __half22float2(*reinterpret_cast<__half2*>(&v.y));
                acc.x += lo.x; acc.y += lo.y; acc.z += hi.x; acc.w += hi.y;
            }
            acc.x *= invn; acc.y *= invn; acc.z *= invn; acc.w *= invn;
            reinterpret_cast<float4*>(s_x0)[tid] = acc;
        }
        __syncthreads();

        float d0 = 0.f, d1 = 0.f, d2 = 0.f;
        if (tid < DD) {
            float xv = s_x0[tid];
            d0 = xv * pU2[tid]; d1 = xv * pB1[tid]; d2 = xv * pB2[tid];
        }
#pragma unroll
        for (int o = 16; o; o >>= 1) {
            d0 += __shfl_xor_sync(0xffffffffu, d0, o);
            d1 += __shfl_xor_sync(0xffffffffu, d1, o);
            d2 += __shfl_xor_sync(0xffffffffu, d2, o);
        }
        if (lane == 0) { s_red[wid][0] = d0; s_red[wid][1] = d1; s_red[wid][2] = d2; }
        __syncthreads();
        if (tid == 0) {
            float a = 0.f, c = 0.f, e = 0.f;
            for (int w = 0; w < 12; w++) { a += s_red[w][0]; c += s_red[w][1]; e += s_red[w][2]; }
            s_b[0] = a; s_b[1] = c; s_b[2] = e;
        }
        __syncthreads();
        float du2 = s_b[0], db1 = s_b[1], db2 = s_b[2];

        int len = s_len;
        int s0 = SS - len;
        float invlen = 1.0f / (float)len;

        // hop 0 (coefs stored UNNORMALIZED; inv folds into output dot)
        float ckq0 = g_ck + du2 + g_c2;
        float es = 0.f, S01 = 0.f, S02 = 0.f;
        for (int s = s0 + tid; s < SS; s += NT) {
            float w = 1.0f - (float)(s - s0) * invlen;
            float e = expf(tanhf(w * s_sv[s] + ckq0));
            float ew = e * w;
            s_c0[s] = ew;
            es += e; S01 += ew * s_t1[s]; S02 += ew * s_t2[s];
        }
#pragma unroll
        for (int o = 16; o; o >>= 1) {
            es  += __shfl_xor_sync(0xffffffffu, es, o);
            S01 += __shfl_xor_sync(0xffffffffu, S01, o);
            S02 += __shfl_xor_sync(0xffffffffu, S02, o);
        }
        if (lane == 0) { s_red[wid][0] = es; s_red[wid][1] = S01; s_red[wid][2] = S02; }
        __syncthreads();
        if (tid == 0) {
            float a = 0.f, c = 0.f, e = 0.f;
            for (int w = 0; w < 12; w++) { a += s_red[w][0]; c += s_red[w][1]; e += s_red[w][2]; }
            float inv0 = 1.0f / (a + (float)s0 * expf(tanhf(ckq0)));
            s_b[0] = inv0;
            s_b[1] = inv0 * c;
            s_b[2] = inv0 * e;
        }
        __syncthreads();
        float inv0 = s_b[0];
        float q1 = s_b[1] + db1 + g_cc1;

        // hop 1
        float ckq1 = g_ck + q1;
        es = 0.f; S01 = 0.f;
        for (int s = s0 + tid; s < SS; s += NT) {
            float w = 1.0f - (float)(s - s0) * invlen;
            float e = expf(tanhf(w * s_sv[s] + ckq1));
            float ew = e * w;
            s_c1[s] = ew;
            es += e; S01 += ew * s_t1[s];
        }
#pragma unroll
        for (int o = 16; o; o >>= 1) {
            es  += __shfl_xor_sync(0xffffffffu, es, o);
            S01 += __shfl_xor_sync(0xffffffffu, S01, o);
        }
        if (lane == 0) { s_red[wid][0] = es; s_red[wid][1] = S01; }
        __syncthreads();
        if (tid == 0) {
            float a = 0.f, c = 0.f;
            for (int w = 0; w < 12; w++) { a += s_red[w][0]; c += s_red[w][1]; }
            float inv1 = 1.0f / (a + (float)s0 * expf(tanhf(ckq1)));
            s_b[3] = inv1;
            s_b[4] = inv1 * c;
        }
        __syncthreads();
        float inv1 = s_b[3];
        float q2 = s_b[4] + s_b[2] + db2 + g_cc2;

        // hop 2
        float ckq2 = g_ck + q2;
        es = 0.f;
        for (int s = s0 + tid; s < SS; s += NT) {
            float w = 1.0f - (float)(s - s0) * invlen;
            float e = expf(tanhf(w * s_sv[s] + ckq2));
            s_c2[s] = e * w;
            es += e;
        }
#pragma unroll
        for (int o = 16; o; o >>= 1) es += __shfl_xor_sync(0xffffffffu, es, o);
        if (lane == 0) s_red[wid][0] = es;
        __syncthreads();
        if (tid == 0) {
            float a = 0.f;
            for (int w = 0; w < 12; w++) a += s_red[w][0];
            s_b[5] = 1.0f / (a + (float)s0 * expf(tanhf(ckq2)));
        }
        __syncthreads();
        float inv2 = s_b[5];

        // single shared gather (unroll 4; coefs unnormalized): am_raw0/1/2
        if (tid < 300) {
            int grp = tid / D4;
            int ch = tid - grp * D4;
            float4 a0 = make_float4(0.f, 0.f, 0.f, 0.f);
            float4 a1 = make_float4(0.f, 0.f, 0.f, 0.f);
            float4 a2 = make_float4(0.f, 0.f, 0.f, 0.f);
            int s = s0 + grp;
            for (; s + 12 < SS; s += 16) {
                int ix[4]; float c0[4], c1[4], c2[4];
#pragma unroll
                for (int j = 0; j < 4; j++) {
                    int ss = s + 4 * j;
                    ix[j] = s_idx[ss]; c0[j] = s_c0[ss]; c1[j] = s_c1[ss]; c2[j] = s_c2[ss];
                }
                uint2 v[4];
#pragma unroll
                for (int j = 0; j < 4; j++) v[j] = g_embh[(size_t)ix[j] * D4 + ch];
#pragma unroll
                for (int j = 0; j < 4; j++) {
                    float2 lo = __half22float2(*reinterpret_cast<__half2*>(&v[j].x));
                    float2 hi = __half22float2(*reinterpret_cast<__half2*>(&v[j].y));
                    a0.x += c0[j] * lo.x; a0.y += c0[j] * lo.y; a0.z += c0[j] * hi.x; a0.w += c0[j] * hi.y;
                    a1.x += c1[j] * lo.x; a1.y += c1[j] * lo.y; a1.z += c1[j] * hi.x; a1.w += c1[j] * hi.y;
                    a2.x += c2[j] * lo.x; a2.y += c2[j] * lo.y; a2.z += c2[j] * hi.x; a2.w += c2[j] * hi.y;
                }
            }
            for (; s < SS; s += 4) {
                float c0 = s_c0[s], c1 = s_c1[s], c2 = s_c2[s];
                uint2 v = g_embh[(size_t)s_idx[s] * D4 + ch];
                float2 lo = __half22float2(*reinterpret_cast<__half2*>(&v.x));
                float2 hi = __half22float2(*reinterpret_cast<__half2*>(&v.y));
                a0.x += c0 * lo.x; a0.y += c0 * lo.y; a0.z += c0 * hi.x; a0.w += c0 * hi.y;
                a1.x += c1 * lo.x; a1.y += c1 * lo.y; a1.z += c1 * hi.x; a1.w += c1 * hi.y;
                a2.x += c2 * lo.x; a2.y += c2 * lo.y; a2.z += c2 * hi.x; a2.w += c2 * hi.y;
            }
            s_part[0][grp][ch] = a0;
            s_part[1][grp][ch] = a1;
            s_part[2][grp][ch] = a2;
        }
        __syncthreads();
        if (tid < 225) {
            int a = tid / D4, ch = tid - a * D4;
            float4 g0 = s_part[a][0][ch], g1 = s_part[a][1][ch];
            float4 g2 = s_part[a][2][ch], g3 = s_part[a][3][ch];
            float4 r;
            r.x = (g0.x + g1.x) + (g2.x + g3.x);
            r.y = (g0.y + g1.y) + (g2.y + g3.y);
            r.z = (g0.z + g1.z) + (g2.z + g3.z);
            r.w = (g0.w + g1.w) + (g2.w + g3.w);
            reinterpret_cast<float4*>(s_am[a])[ch] = r;
        }
        __syncthreads();

        // output: out[row] = inv2*(M2.am2r) + inv1*(M1.am1r) + inv0*(M0.am0r)
        //                  + Mx.x0 + cvec
        {
            int p = wid >> 2, src = wid & 3;
            const float* M = (src == 0) ? (pM2 + p * DD) : (src == 1) ? (pM1 + p * DD)
                           : (src == 2) ? (pM0 + p * DD) : (pMX + p * DD);
            const float* vec = (src == 0) ? s_am[2] : (src == 1) ? s_am[1]
                             : (src == 2) ? s_am[0] : s_x0;
            float scale = (src == 0) ? inv2 : (src == 1) ? inv1
                        : (src == 2) ? inv0 : 1.0f;
            float acc = 0.f;
            for (int d = lane; d < DD; d += 32) acc += M[d] * vec[d];
#pragma unroll
            for (int o = 16; o; o >>= 1) acc += __shfl_xor_sync(0xffffffffu, acc, o);
            if (lane == 0) s_red[wid][0] = acc * scale;
        }
        __syncthreads();
        if (tid < PP) {
            out[row * PP + tid] = pCV[tid] + (s_red[tid * 4][0] + s_red[tid * 4 + 1][0])
                                           + (s_red[tid * 4 + 2][0] + s_red[tid * 4 + 3][0]);
        }
        __syncthreads();
    }
}

// ---------------- launch -----------------
extern "C" void kernel_launch(void* const* d_in, const int* in_sizes, int n_in,
                              void* d_out, int out_size) {
    const int*   text = (const int*)d_in[0];
    const int*   asp  = (const int*)d_in[1];
    const float* emb  = (const float*)d_in[2];
    const float* Wx   = (const float*)d_in[3];
    const float* bx   = (const float*)d_in[4];
    const float* Wk   = (const float*)d_in[5];
    const float* bk   = (const float*)d_in[6];
    const float* Wq   = (const float*)d_in[7];
    const float* bq   = (const float*)d_in[8];
    const float* wmlp = (const float*)d_in[9];
    const float* Wp   = (const float*)d_in[10];
    const float* bp   = (const float*)d_in[11];
    const float* Wd   = (const float*)d_in[12];
    const float* bd   = (const float*)d_in[13];
    float* out = (float*)d_out;

    k_all<<<NBLK, NT>>>(Wq, Wk, Wp, Wx, Wd, wmlp, bk, bq, bp, bx, bd,
                        emb, text, asp, out);
}